// round 11
// baseline (speedup 1.0000x reference)
#include <cuda_runtime.h>
#include <cuda_bf16.h>
#include <math.h>
#include <stdint.h>

#define T_LEN 88200
#define NB 8
#define TC 1378
#define IN_GAIN 1.8197008586099834f
#define ABOVE_SLOPE 0.98500749625187401f
#define BELOW_SLOPE 0.76019184652277820f

// ---------------- scratch ----------------
__device__ float g_mh[NB * 2 * T_LEN];
__device__ float g_bands[NB * 3 * 2 * T_LEN];   // [b][band][c][t] band0=high,1=mid,2=low
__device__ float g_xrms[24 * TC];
__device__ float g_env[24 * TC];
__device__ float g_comb[NB * 2 * T_LEN];
__device__ __nv_bfloat16 g_bA[(size_t)NB * T_LEN * 64];   // activations [b][t][64] bf16
__device__ __nv_bfloat16 g_bB[(size_t)NB * T_LEN * 64];
__device__ __nv_bfloat16 g_wtb[3 * 3 * 64 * 64];          // weights [layer][tap][oc][ic] bf16
__device__ float g_w0p[64 * 8];                 // conv0 weights packed [oc][w0..w5,bias,0]
__device__ float g_w4p[3 * 32 * 4];             // conv4 weights packed [k][icpair][4]

// ---------------- helpers ----------------
__device__ __forceinline__ uint32_t s2u(const void* p) {
    uint32_t a;
    asm("{ .reg .u64 t; cvta.to.shared.u64 t, %1; cvt.u32.u64 %0, t; }" : "=r"(a) : "l"(p));
    return a;
}
__device__ __forceinline__ float gelu_tanh(float x) {
    float u = 0.7978845608028654f * fmaf(0.044715f * x, x * x, x);
    float t; asm("tanh.approx.f32 %0, %1;" : "=f"(t) : "f"(u));
    return 0.5f * x * (1.0f + t);
}
__device__ __forceinline__ uint32_t pack_bf16(float lo, float hi) {
    uint32_t r;
    asm("cvt.rn.satfinite.bf16x2.f32 %0, %1, %2;" : "=r"(r) : "f"(hi), "f"(lo));
    return r;
}
__device__ __forceinline__ float knee_fn(float x, float thr, float slope, float k) {
    float diff = x - thr, kh = 0.5f * k;
    if (fabsf(diff) <= kh) { float u = diff + kh; return slope * u * u / (2.0f * k); }
    return diff > kh ? slope * diff : 0.0f;
}

// ---------------- prep kernels ----------------
__global__ void prep_wtb_kernel(const float* __restrict__ w1, const float* __restrict__ w2,
                                const float* __restrict__ w3, __nv_bfloat16* __restrict__ wtb)
{
    int i = blockIdx.x * 256 + threadIdx.x;
    if (i >= 3 * 12288) return;
    int l = i / 12288, j = i - l * 12288;
    int tap = j >> 12, e = j & 4095;
    int oc = e >> 6, ic = e & 63;
    const float* src = (l == 0) ? w1 : (l == 1) ? w2 : w3;
    wtb[i] = __float2bfloat16(src[oc * 192 + ic * 3 + tap]);
}

__global__ void prep_small_kernel(const float* __restrict__ w0, const float* __restrict__ b0,
                                  const float* __restrict__ w4,
                                  float* __restrict__ w0p, float* __restrict__ w4p)
{
    int i = threadIdx.x;
    if (i < 64) {
        #pragma unroll
        for (int q = 0; q < 6; q++) w0p[i * 8 + q] = w0[i * 6 + q];
        w0p[i * 8 + 6] = b0[i];
        w0p[i * 8 + 7] = 0.0f;
    }
    if (i < 96) {   // (k, icpair)
        int k = i / 32, jp = i % 32;
        w4p[i * 4 + 0] = w4[(2 * jp) * 3 + k];
        w4p[i * 4 + 1] = w4[(2 * jp + 1) * 3 + k];
        w4p[i * 4 + 2] = w4[192 + (2 * jp) * 3 + k];
        w4p[i * 4 + 3] = w4[192 + (2 * jp + 1) * 3 + k];
    }
}

// ---------------- FIR crossover: rolling window + vec weight loads ---------
template <int STAGE>
__global__ void __launch_bounds__(256) fir_kernel(
    const float* __restrict__ in, const float* __restrict__ wA,
    const float* __restrict__ wB, float* __restrict__ bands, float* __restrict__ mh)
{
    __shared__ __align__(16) float swa[512], swb[512], sx[2576];
    const int row = blockIdx.y, b = row >> 1, c = row & 1;
    const int t0 = blockIdx.x * 2048;
    const int tid = threadIdx.x;

    for (int i = tid; i < 512; i += 256) { swa[i] = wA[i]; swb[i] = wB[i]; }
    const float gain = (STAGE == 1) ? IN_GAIN : 1.0f;
    const float* xin = (STAGE == 1) ? (in + row * T_LEN) : (mh + row * T_LEN);
    for (int i = tid; i < 2559; i += 256) {
        int g = t0 - 511 + i;
        sx[i] = (g >= 0 && g < T_LEN) ? xin[g] * gain : 0.0f;
    }
    __syncthreads();

    float aA[8] = {0,0,0,0,0,0,0,0}, aB[8] = {0,0,0,0,0,0,0,0};
    const int base = tid * 8;                         // 32B aligned
    float4 x0 = *(const float4*)&sx[base];
    float4 x1 = *(const float4*)&sx[base + 4];
    #pragma unroll 2
    for (int k0 = 0; k0 < 512; k0 += 8) {
        float4 x2 = *(const float4*)&sx[base + k0 + 8];
        float4 x3 = *(const float4*)&sx[base + k0 + 12];   // tail values unused math-wise
        float xw[16];
        xw[0]=x0.x; xw[1]=x0.y; xw[2]=x0.z; xw[3]=x0.w;
        xw[4]=x1.x; xw[5]=x1.y; xw[6]=x1.z; xw[7]=x1.w;
        xw[8]=x2.x; xw[9]=x2.y; xw[10]=x2.z; xw[11]=x2.w;
        xw[12]=x3.x; xw[13]=x3.y; xw[14]=x3.z; xw[15]=x3.w;
        float4 wa0 = *(const float4*)&swa[k0];
        float4 wa1 = *(const float4*)&swa[k0 + 4];
        float4 wb0 = *(const float4*)&swb[k0];
        float4 wb1 = *(const float4*)&swb[k0 + 4];
        float wa[8] = {wa0.x, wa0.y, wa0.z, wa0.w, wa1.x, wa1.y, wa1.z, wa1.w};
        float wb[8] = {wb0.x, wb0.y, wb0.z, wb0.w, wb1.x, wb1.y, wb1.z, wb1.w};
        #pragma unroll
        for (int kk = 0; kk < 8; kk++) {
            #pragma unroll
            for (int j = 0; j < 8; j++) {
                float v = xw[kk + j];
                aA[j] = fmaf(wa[kk], v, aA[j]);
                aB[j] = fmaf(wb[kk], v, aB[j]);
            }
        }
        x0 = x2; x1 = x3;
    }

    float* outA;
    float* outB;
    if (STAGE == 1) {
        outA = bands + ((size_t)(b * 3 + 2) * 2 + c) * T_LEN;
        outB = mh + (size_t)row * T_LEN;
    } else {
        outA = bands + ((size_t)(b * 3 + 1) * 2 + c) * T_LEN;
        outB = bands + ((size_t)(b * 3 + 0) * 2 + c) * T_LEN;
    }
    #pragma unroll
    for (int j = 0; j < 8; j++) {
        int t = t0 + base + j;
        if (t < T_LEN) { outA[t] = aA[j]; outB[t] = aB[j]; }
    }
}

// ---------------- per-band RMS ----------------
__global__ void xrms_kernel(const float* __restrict__ bands, float* __restrict__ xrms)
{
    const int row = blockIdx.x;
    const int warp = threadIdx.x >> 5, lane = threadIdx.x & 31;
    const int j = blockIdx.y * 8 + warp;
    if (j >= TC) return;
    const float* p0 = bands + (size_t)row * 2 * T_LEN;
    const float* p1 = p0 + T_LEN;
    int base = j * 64;
    float v0 = p0[base + lane], v1 = p0[base + lane + 32];
    float u0 = p1[base + lane], u1 = p1[base + lane + 32];
    float s = v0*v0 + v1*v1 + u0*u0 + u1*u1;
    #pragma unroll
    for (int o = 16; o > 0; o >>= 1) s += __shfl_xor_sync(0xffffffffu, s, o);
    if (lane == 0) xrms[row * TC + j] = sqrtf(s * (1.0f / 128.0f) + 1e-7f);
}

// ---------------- release envelope: parallel max-scan ----------------
__global__ void __launch_bounds__(256) envscan_kernel(
    const float* __restrict__ xrms, const float* __restrict__ rel_alphas,
    float* __restrict__ env)
{
    __shared__ float wtot[8];
    const int r = blockIdx.x;
    const int tid = threadIdx.x, lane = tid & 31, warp = tid >> 5;
    float kk = 1.0f - rel_alphas[r >> 3];   // reference repeat quirk: rel[r/8]
    float lg = log2f(kk);                    // negative
    const float* x = xrms + r * TC;

    float loc[6];
    float run = 0.0f;
    #pragma unroll
    for (int i = 0; i < 6; i++) {
        int n = tid * 6 + i;
        float z = (n < TC) ? x[n] * exp2f(-lg * (float)n) : 0.0f;
        run = fmaxf(run, z);
        loc[i] = run;
    }
    float inc = run;
    #pragma unroll
    for (int o = 1; o < 32; o <<= 1) {
        float v = __shfl_up_sync(0xffffffffu, inc, o);
        if (lane >= o) inc = fmaxf(inc, v);
    }
    float excl_in_warp = __shfl_up_sync(0xffffffffu, inc, 1);
    if (lane == 0) excl_in_warp = 0.0f;
    if (lane == 31) wtot[warp] = inc;
    __syncthreads();
    float wpre = 0.0f;
    #pragma unroll
    for (int w = 0; w < 8; w++) if (w < warp) wpre = fmaxf(wpre, wtot[w]);
    float E = fmaxf(wpre, excl_in_warp);

    #pragma unroll
    for (int i = 0; i < 6; i++) {
        int n = tid * 6 + i;
        if (n < TC) {
            float ez = fmaxf(E, loc[i]);
            env[r * TC + n] = ez * exp2f(lg * (float)n);
        }
    }
}

// ---------------- gain + band combine ----------------
__global__ void combine_kernel(const float* __restrict__ bands, const float* __restrict__ env,
                               const float* __restrict__ params, const float* __restrict__ knee_db,
                               float* __restrict__ comb)
{
    const int t = blockIdx.x * 256 + threadIdx.x;
    const int b = blockIdx.y;
    if (t >= T_LEN) return;
    const float* pp = params + b * 7;
    const float knee = *knee_db;

    float pos = (float)t * (1377.0f / 88199.0f);
    int i0 = (int)floorf(pos);
    if (i0 > TC - 2) i0 = TC - 2;
    if (i0 < 0) i0 = 0;
    float frac = pos - (float)i0;

    float acc0 = 0.f, acc1 = 0.f;
    #pragma unroll
    for (int band = 0; band < 3; band++) {
        int r = b * 3 + band;
        float e0 = env[r * TC + i0], e1 = env[r * TC + i0 + 1];
        float e = e0 * (1.0f - frac) + e1 * frac;
        float edb = 20.0f * log10f(e + 1e-7f);
        float ta = pp[3 - band], tb = pp[6 - band];
        float sa = (band == 0) ? 1.0f : ABOVE_SLOPE;
        float gdb = -knee_fn(edb, ta, sa, knee) + knee_fn(-edb, -tb, BELOW_SLOPE, knee);
        float og = (band == 1) ? 5.7f : 10.3f;
        float v = fminf(fmaxf(gdb + og, -80.0f), 40.0f);
        float g = exp10f(v * 0.05f);
        const float* bb = bands + (size_t)(r * 2) * T_LEN;
        acc0 = fmaf(bb[t], g, acc0);
        acc1 = fmaf(bb[T_LEN + t], g, acc1);
    }
    comb[(size_t)(b * 2) * T_LEN + t] = acc0;
    comb[(size_t)(b * 2 + 1) * T_LEN + t] = acc1;
}

// ---------------- conv0: 2->64, k3 d1, gelu, writes bf16 [b][t][64] --------
__global__ void __launch_bounds__(256) conv0_kernel(
    const float* __restrict__ comb, const float* __restrict__ w0p,
    __nv_bfloat16* __restrict__ out)
{
    __shared__ float4 sw[128];
    const int b = blockIdx.y;
    const int t = blockIdx.x * 256 + threadIdx.x;
    for (int i = threadIdx.x; i < 128; i += 256) sw[i] = ((const float4*)w0p)[i];
    __syncthreads();
    if (t >= T_LEN) return;

    float xv[6];
    const float* c0 = comb + (size_t)(b * 2) * T_LEN;
    const float* c1 = c0 + T_LEN;
    #pragma unroll
    for (int k = 0; k < 3; k++) {
        int g = t - 1 + k;
        bool ok = (g >= 0 && g < T_LEN);
        xv[k]     = ok ? c0[g] : 0.0f;
        xv[3 + k] = ok ? c1[g] : 0.0f;
    }
    uint32_t r[32];
    #pragma unroll
    for (int p = 0; p < 32; p++) {
        float4 wA0 = sw[(2*p)*2], wB0 = sw[(2*p)*2 + 1];
        float4 wA1 = sw[(2*p+1)*2], wB1 = sw[(2*p+1)*2 + 1];
        float a0 = wB0.z, a1 = wB1.z;
        a0 = fmaf(wA0.x, xv[0], a0); a0 = fmaf(wA0.y, xv[1], a0); a0 = fmaf(wA0.z, xv[2], a0);
        a0 = fmaf(wA0.w, xv[3], a0); a0 = fmaf(wB0.x, xv[4], a0); a0 = fmaf(wB0.y, xv[5], a0);
        a1 = fmaf(wA1.x, xv[0], a1); a1 = fmaf(wA1.y, xv[1], a1); a1 = fmaf(wA1.z, xv[2], a1);
        a1 = fmaf(wA1.w, xv[3], a1); a1 = fmaf(wB1.x, xv[4], a1); a1 = fmaf(wB1.y, xv[5], a1);
        r[p] = pack_bf16(gelu_tanh(a0), gelu_tanh(a1));
    }
    uint4* dst = (uint4*)(out + ((size_t)b * T_LEN + t) * 64);
    #pragma unroll
    for (int q = 0; q < 8; q++) dst[q] = ((uint4*)r)[q];
}

// ---------------- conv64 via mma.sync bf16, ldmatrix for A and B -----------
template <int DIL>
__global__ void __launch_bounds__(256) conv64_mma(
    const __nv_bfloat16* __restrict__ in,   // [b][t][64]
    const __nv_bfloat16* __restrict__ wtb,  // [tap][oc][ic] bf16
    const float* __restrict__ bias,
    __nv_bfloat16* __restrict__ out)
{
    constexpr int AROWS = 128 + 2 * DIL;
    extern __shared__ __align__(16) char sm[];
    char* sA = sm;                         // AROWS x 144B
    char* sB = sm + AROWS * 144;           // 192 x 144B
    __shared__ float sbias[64];

    const int b = blockIdx.y;
    const int t0 = blockIdx.x * 128;
    const int tid = threadIdx.x, lane = tid & 31, warp = tid >> 5;

    if (tid < 64) sbias[tid] = bias[tid];

    for (int i = tid; i < 1536; i += 256) {          // B: 192 rows x 8 chunks
        int row = i >> 3, ch = i & 7;
        *(uint4*)(sB + row * 144 + ch * 16) = ((const uint4*)wtb)[i];
    }
    for (int i = tid; i < AROWS * 8; i += 256) {     // A
        int row = i >> 3, ch = i & 7;
        int g = t0 - DIL + row;
        uint4 v = make_uint4(0u, 0u, 0u, 0u);
        if (g >= 0 && g < T_LEN)
            v = *(const uint4*)(in + ((size_t)b * T_LEN + g) * 64 + ch * 8);
        *(uint4*)(sA + row * 144 + ch * 16) = v;
    }
    __syncthreads();

    const uint32_t sAu = s2u(sA), sBu = s2u(sB);
    float acc[8][4];
    #pragma unroll
    for (int nt = 0; nt < 8; nt++)
        #pragma unroll
        for (int q = 0; q < 4; q++) acc[nt][q] = 0.0f;

    const int mrow = warp * 16;
    // ldmatrix A: per-thread source row/col within the m16k16 tile
    const int lrow = (lane & 7) + ((lane >> 3) & 1) * 8;
    const int lcol = (lane >> 4) * 16;
    // ldmatrix B (x2): lanes 0-7 -> tile0 rows (k lo), 8-15 -> tile1 rows (k hi)
    const uint32_t bfb = sBu + (uint32_t)((lane & 7) * 144 + ((lane >> 3) & 1) * 16);

    #pragma unroll
    for (int tap = 0; tap < 3; tap++) {
        const uint32_t abase = sAu + (uint32_t)((mrow + tap * DIL + lrow) * 144 + lcol);
        const uint32_t bbase = bfb + (uint32_t)(tap * 9216);
        #pragma unroll
        for (int kc = 0; kc < 4; kc++) {
            uint32_t a0, a1, a2, a3;
            asm volatile("ldmatrix.sync.aligned.m8n8.x4.shared.b16 {%0,%1,%2,%3}, [%4];"
                : "=r"(a0), "=r"(a1), "=r"(a2), "=r"(a3) : "r"(abase + kc * 32));
            #pragma unroll
            for (int nt = 0; nt < 8; nt++) {
                uint32_t b0, b1;
                asm volatile("ldmatrix.sync.aligned.m8n8.x2.shared.b16 {%0,%1}, [%2];"
                    : "=r"(b0), "=r"(b1) : "r"(bbase + nt * 1152 + kc * 32));
                asm volatile("mma.sync.aligned.m16n8k16.row.col.f32.bf16.bf16.f32 "
                    "{%0,%1,%2,%3}, {%4,%5,%6,%7}, {%8,%9}, {%0,%1,%2,%3};"
                    : "+f"(acc[nt][0]), "+f"(acc[nt][1]), "+f"(acc[nt][2]), "+f"(acc[nt][3])
                    : "r"(a0), "r"(a1), "r"(a2), "r"(a3), "r"(b0), "r"(b1));
            }
        }
    }

    // epilogue: c0,c1 -> (row=lane/4, col=(lane%4)*2); c2,c3 -> row+8
    const int r1 = mrow + (lane >> 2);
    const int c0 = (lane & 3) * 2;
    const int t1 = t0 + r1, t2 = t1 + 8;
    __nv_bfloat16* ob = out + (size_t)b * T_LEN * 64;
    #pragma unroll
    for (int nt = 0; nt < 8; nt++) {
        int col = nt * 8 + c0;
        float bv0 = sbias[col], bv1 = sbias[col + 1];
        if (t1 < T_LEN) {
            uint32_t pk = pack_bf16(gelu_tanh(acc[nt][0] + bv0), gelu_tanh(acc[nt][1] + bv1));
            *(uint32_t*)(ob + (size_t)t1 * 64 + col) = pk;
        }
        if (t2 < T_LEN) {
            uint32_t pk = pack_bf16(gelu_tanh(acc[nt][2] + bv0), gelu_tanh(acc[nt][3] + bv1));
            *(uint32_t*)(ob + (size_t)t2 * 64 + col) = pk;
        }
    }
}

// ---------------- conv4 (64->2, k3 d1) + dry/wet mix -----------------------
// sxw row stride = 36 words (144B): with the lane rotation the bank index is
// (5*lane + const) mod 32 -> conflict-free; 36 words keeps uint4 alignment.
__global__ void __launch_bounds__(128) conv4_kernel(
    const __nv_bfloat16* __restrict__ in, const float* __restrict__ w4p,
    const float* __restrict__ b4, const float* __restrict__ comb,
    const float* __restrict__ audio, const float* __restrict__ params,
    float* __restrict__ outp)
{
    __shared__ uint32_t sxw[130 * 36];
    __shared__ float4 sw4p[96];
    const int b = blockIdx.y;
    const int t0 = blockIdx.x * 128;
    const int tid = threadIdx.x, lane = tid & 31;

    for (int i = tid; i < 96; i += 128) sw4p[i] = ((const float4*)w4p)[i];
    for (int i = tid; i < 130 * 8; i += 128) {
        int row = i >> 3, ch = i & 7;
        int g = t0 - 1 + row;
        uint4 v = make_uint4(0u, 0u, 0u, 0u);
        if (g >= 0 && g < T_LEN)
            v = *(const uint4*)(in + ((size_t)b * T_LEN + g) * 64 + ch * 8);
        ((uint4*)sxw)[row * 9 + ch] = v;
    }
    __syncthreads();

    const int t = t0 + tid;
    float a0 = __ldg(&b4[0]), a1 = __ldg(&b4[1]);
    #pragma unroll
    for (int k = 0; k < 3; k++) {
        const uint32_t* xr = &sxw[(tid + k) * 36];
        #pragma unroll 8
        for (int jj = 0; jj < 32; jj++) {
            int j = (jj + lane) & 31;
            uint32_t xp = xr[j];
            float2 xv = __bfloat1622float2(*(const __nv_bfloat162*)&xp);
            float4 w = sw4p[k * 32 + j];
            a0 = fmaf(w.x, xv.x, fmaf(w.y, xv.y, a0));
            a1 = fmaf(w.z, xv.x, fmaf(w.w, xv.y, a1));
        }
    }
    if (t < T_LEN) {
        float amt = __ldg(&params[b * 7]);
        size_t i0 = (size_t)(b * 2) * T_LEN + t;
        size_t i1 = (size_t)(b * 2 + 1) * T_LEN + t;
        outp[i0] = (1.0f - amt) * audio[i0] + amt * (comb[i0] + a0);
        outp[i1] = (1.0f - amt) * audio[i1] + amt * (comb[i1] + a1);
    }
}

// ---------------------------------------------------------------------------
extern "C" void kernel_launch(void* const* d_in, const int* in_sizes, int n_in,
                              void* d_out, int out_size)
{
    (void)in_sizes; (void)n_in; (void)out_size;
    const float* audio     = (const float*)d_in[0];
    const float* params    = (const float*)d_in[1];
    const float* rel       = (const float*)d_in[2];
    const float* knee_db   = (const float*)d_in[3];
    const float* ir_low_lp = (const float*)d_in[4];
    const float* ir_low_hp = (const float*)d_in[5];
    const float* ir_hi_lp  = (const float*)d_in[6];
    const float* ir_hi_hp  = (const float*)d_in[7];
    const float* w0 = (const float*)d_in[8];
    const float* b0 = (const float*)d_in[9];
    const float* w1 = (const float*)d_in[10];  const float* b1 = (const float*)d_in[11];
    const float* w2 = (const float*)d_in[12];  const float* b2 = (const float*)d_in[13];
    const float* w3 = (const float*)d_in[14];  const float* b3 = (const float*)d_in[15];
    const float* w4 = (const float*)d_in[16];  const float* b4 = (const float*)d_in[17];
    float* out = (float*)d_out;

    float *bands, *mh, *xrms, *env, *comb, *w0p, *w4p;
    __nv_bfloat16 *bA, *bB, *wtb;
    cudaGetSymbolAddress((void**)&bands, g_bands);
    cudaGetSymbolAddress((void**)&mh,    g_mh);
    cudaGetSymbolAddress((void**)&xrms,  g_xrms);
    cudaGetSymbolAddress((void**)&env,   g_env);
    cudaGetSymbolAddress((void**)&comb,  g_comb);
    cudaGetSymbolAddress((void**)&bA,    g_bA);
    cudaGetSymbolAddress((void**)&bB,    g_bB);
    cudaGetSymbolAddress((void**)&wtb,   g_wtb);
    cudaGetSymbolAddress((void**)&w0p,   g_w0p);
    cudaGetSymbolAddress((void**)&w4p,   g_w4p);

    // dynamic smem: A rows x 144B + B 192 x 144B  (all < 48KB, no opt-in)
    const int smem2 = (128 + 4)  * 144 + 192 * 144;   // 46656
    const int smem4 = (128 + 8)  * 144 + 192 * 144;   // 47232
    const int smem8 = (128 + 16) * 144 + 192 * 144;   // 48384

    // prep (independent)
    prep_wtb_kernel<<<(3 * 12288 + 255) / 256, 256>>>(w1, w2, w3, wtb);
    prep_small_kernel<<<1, 128>>>(w0, b0, w4, w0p, w4p);

    // crossover FIRs
    fir_kernel<1><<<dim3(44, 16), 256>>>(audio, ir_low_lp, ir_low_hp, bands, mh);
    fir_kernel<2><<<dim3(44, 16), 256>>>(nullptr, ir_hi_lp, ir_hi_hp, bands, mh);

    // envelope + combine
    xrms_kernel<<<dim3(24, (TC + 7) / 8), 256>>>(bands, xrms);
    envscan_kernel<<<24, 256>>>(xrms, rel, env);
    combine_kernel<<<dim3((T_LEN + 255) / 256, NB), 256>>>(bands, env, params, knee_db, comb);

    // TCN
    conv0_kernel<<<dim3((T_LEN + 255) / 256, NB), 256>>>(comb, w0p, bA);
    conv64_mma<2><<<dim3((T_LEN + 127) / 128, NB), 256, smem2>>>(bA, wtb,          b1, bB);
    conv64_mma<4><<<dim3((T_LEN + 127) / 128, NB), 256, smem4>>>(bB, wtb + 12288,  b2, bA);
    conv64_mma<8><<<dim3((T_LEN + 127) / 128, NB), 256, smem8>>>(bA, wtb + 24576,  b3, bB);

    // final conv + mix
    conv4_kernel<<<dim3((T_LEN + 127) / 128, NB), 128>>>(bB, w4p, b4, comb, audio, params, out);
}